// round 2
// baseline (speedup 1.0000x reference)
#include <cuda_runtime.h>

// TPThird: e3nn-style tensor product, Z=50000 samples.
// x1: (Z,108) = [0e:48 | 1o:10x3 | 1e:10x3], x2: (Z,9) = [0e | 1o:3 | 2e:5]
// weights: (Z,4344), out: (Z,156) = [r0e:48 | r1o:30 | r1e:30 | r0o:48]

#define NS 48
#define NV 10
#define WNUM 4344
#define OUTDIM 156

// weight offsets (floats) within a sample's 4344-float blob
#define OFF_W00   0
#define OFF_W01   2304
#define OFF_W10   2784
#define OFF_W110  2884
#define OFF_W112  3364
#define OFF_W12   3464
#define OFF_W20   3564
#define OFF_W211  3664
#define OFF_W213  3764
#define OFF_W22   4244

// normalization constants
#define N0E  0.13130643285972254f   // sqrt(1/58)
#define N1O  0.19611613513818404f   // sqrt(3/78)
#define N1E  0.31622776601683794f   // sqrt(1/10)
#define N0O  0.31622776601683794f   // sqrt(1/10)
#define ISQ3 0.57735026918962576f   // 1/sqrt(3)
#define ISQ6 0.40824829046386302f   // 1/sqrt(6)
#define S10  0.31622776601683794f   // 1/sqrt(10)
#define S30  0.18257418583505537f   // 1/sqrt(30)

__global__ __launch_bounds__(256) void tp_third_kernel(
    const float* __restrict__ x1,
    const float* __restrict__ x2,
    const float* __restrict__ wts,
    float* __restrict__ out)
{
    const int z = blockIdx.x;
    const int t = threadIdx.x;

    __shared__ float sw[WNUM];       // 17376 B weight stage
    __shared__ float sx1[108];
    __shared__ float sx2[9];
    __shared__ float s_a00[48];      // N0E * x2_0e * x1_0e[u]           -> r0e
    __shared__ float s_a110[10];     // N0E*ISQ3 * dot(x1_1o[u], x2_1o)  -> r0e
    __shared__ float s_a213[10];     // N0O*ISQ3 * dot(x1_1e[u], x2_1o)  -> r0o
    __shared__ float s_v10[30];      // N1O*ISQ3 * x2_0e * x1_1o[u]      -> r1o
    __shared__ float s_v12[30];      // N1O * w3j121(x1_1o[u], x2_2e)    -> r1o
    __shared__ float s_v211[30];     // N1O/sqrt6 * cross(x1_1e[u],x2_1o)-> r1o
    __shared__ float s_v112[30];     // N1E/sqrt6 * cross(x1_1o[u],x2_1o)-> r1e
    __shared__ float s_v20[30];      // N1E*ISQ3 * x2_0e * x1_1e[u]      -> r1e
    __shared__ float s_v22[30];      // N1E * w3j121(x1_1e[u], x2_2e)    -> r1e

    // ---- phase 1: coalesced stage of this sample's weights + inputs ----
    {
        const float4* __restrict__ wsrc =
            reinterpret_cast<const float4*>(wts + (size_t)z * WNUM);
        float4* wdst = reinterpret_cast<float4*>(sw);
        #pragma unroll
        for (int i = t; i < WNUM / 4; i += 256) wdst[i] = wsrc[i];
    }
    if (t < 108)       sx1[t]       = x1[(size_t)z * 108 + t];
    else if (t < 117)  sx2[t - 108] = x2[(size_t)z * 9 + (t - 108)];
    __syncthreads();

    // ---- phase 2: precompute left-operand vectors ----
    const float e0 = sx2[0];
    const float b0 = sx2[1], b1 = sx2[2], b2 = sx2[3];
    const float c0 = sx2[4], c1 = sx2[5], c2 = sx2[6], c3 = sx2[7], c4 = sx2[8];

    if (t < 48) {
        s_a00[t] = N0E * e0 * sx1[t];
    } else if (t < 58) {
        const int u = t - 48;
        const float a0 = sx1[48 + u * 3 + 0];
        const float a1 = sx1[48 + u * 3 + 1];
        const float a2 = sx1[48 + u * 3 + 2];
        s_a110[u] = N0E * ISQ3 * (a0 * b0 + a1 * b1 + a2 * b2);
        s_v10[u * 3 + 0] = N1O * ISQ3 * e0 * a0;
        s_v10[u * 3 + 1] = N1O * ISQ3 * e0 * a1;
        s_v10[u * 3 + 2] = N1O * ISQ3 * e0 * a2;
        // W3J111 contraction = cross(a, b) / sqrt(6)
        s_v112[u * 3 + 0] = N1E * ISQ6 * (a1 * b2 - a2 * b1);
        s_v112[u * 3 + 1] = N1E * ISQ6 * (a2 * b0 - a0 * b2);
        s_v112[u * 3 + 2] = N1E * ISQ6 * (a0 * b1 - a1 * b0);
        // W3J121 contraction (explicit 11-entry bilinear)
        const float g0 = S10 * a2 * c0 - S30 * a0 * c2 - S10 * a0 * c4 + S10 * a1 * c1;
        const float g1 = S10 * a2 * c3 + S10 * a0 * c1 + 2.0f * S30 * a1 * c2;
        const float g2 = -S30 * a2 * c2 + S10 * a2 * c4 + S10 * a0 * c0 + S10 * a1 * c3;
        s_v12[u * 3 + 0] = N1O * g0;
        s_v12[u * 3 + 1] = N1O * g1;
        s_v12[u * 3 + 2] = N1O * g2;
    } else if (t < 68) {
        const int u = t - 58;
        const float a0 = sx1[78 + u * 3 + 0];
        const float a1 = sx1[78 + u * 3 + 1];
        const float a2 = sx1[78 + u * 3 + 2];
        s_a213[u] = N0O * ISQ3 * (a0 * b0 + a1 * b1 + a2 * b2);
        s_v20[u * 3 + 0] = N1E * ISQ3 * e0 * a0;
        s_v20[u * 3 + 1] = N1E * ISQ3 * e0 * a1;
        s_v20[u * 3 + 2] = N1E * ISQ3 * e0 * a2;
        s_v211[u * 3 + 0] = N1O * ISQ6 * (a1 * b2 - a2 * b1);
        s_v211[u * 3 + 1] = N1O * ISQ6 * (a2 * b0 - a0 * b2);
        s_v211[u * 3 + 2] = N1O * ISQ6 * (a0 * b1 - a1 * b0);
        const float g0 = S10 * a2 * c0 - S30 * a0 * c2 - S10 * a0 * c4 + S10 * a1 * c1;
        const float g1 = S10 * a2 * c3 + S10 * a0 * c1 + 2.0f * S30 * a1 * c2;
        const float g2 = -S30 * a2 * c2 + S10 * a2 * c4 + S10 * a0 * c0 + S10 * a1 * c3;
        s_v22[u * 3 + 0] = N1E * g0;
        s_v22[u * 3 + 1] = N1E * g1;
        s_v22[u * 3 + 2] = N1E * g2;
    }
    __syncthreads();

    // ---- phase 3: per-output-element column matvecs from smem ----
    float* __restrict__ o = out + (size_t)z * OUTDIM;

    if (t < 48) {
        // r0e[w] : w00 (48x48) + w110 (10x48)
        const int w = t;
        float acc = 0.0f;
        #pragma unroll
        for (int u = 0; u < 48; u++) acc += s_a00[u] * sw[OFF_W00 + u * 48 + w];
        #pragma unroll
        for (int u = 0; u < 10; u++) acc += s_a110[u] * sw[OFF_W110 + u * 48 + w];
        o[w] = acc;
    } else if (t < 96) {
        // r0o[w] : w213 (10x48)
        const int w = t - 48;
        float acc = 0.0f;
        #pragma unroll
        for (int u = 0; u < 10; u++) acc += s_a213[u] * sw[OFF_W213 + u * 48 + w];
        o[108 + w] = acc;
    } else if (t < 126) {
        // r1o[w,j] : w01 (48x10, outer with x2_1o) + w10 + w12 + w211 (10x10)
        const int idx = t - 96;
        const int w = idx / 3, j = idx % 3;
        const float c01 = N1O * ISQ3 * sx2[1 + j];
        float ts = 0.0f;
        #pragma unroll
        for (int u = 0; u < 48; u++) ts += sx1[u] * sw[OFF_W01 + u * 10 + w];
        float acc = c01 * ts;
        #pragma unroll
        for (int u = 0; u < 10; u++) {
            acc += s_v10[u * 3 + j]  * sw[OFF_W10  + u * 10 + w];
            acc += s_v12[u * 3 + j]  * sw[OFF_W12  + u * 10 + w];
            acc += s_v211[u * 3 + j] * sw[OFF_W211 + u * 10 + w];
        }
        o[48 + w * 3 + j] = acc;
    } else if (t < 156) {
        // r1e[w,j] : w112 + w20 + w22 (10x10)
        const int idx = t - 126;
        const int w = idx / 3, j = idx % 3;
        float acc = 0.0f;
        #pragma unroll
        for (int u = 0; u < 10; u++) {
            acc += s_v112[u * 3 + j] * sw[OFF_W112 + u * 10 + w];
            acc += s_v20[u * 3 + j]  * sw[OFF_W20  + u * 10 + w];
            acc += s_v22[u * 3 + j]  * sw[OFF_W22  + u * 10 + w];
        }
        o[78 + w * 3 + j] = acc;
    }
}

extern "C" void kernel_launch(void* const* d_in, const int* in_sizes, int n_in,
                              void* d_out, int out_size) {
    const float* x1  = (const float*)d_in[0];
    const float* x2  = (const float*)d_in[1];
    const float* wts = (const float*)d_in[2];
    float* out = (float*)d_out;
    const int Z = in_sizes[0] / 108;
    tp_third_kernel<<<Z, 256>>>(x1, x2, wts, out);
}

// round 3
// speedup vs baseline: 1.0670x; 1.0670x over previous
#include <cuda_runtime.h>

// TPThird: e3nn-style tensor product, Z=50000 samples.
// x1: (Z,108) = [0e:48 | 1o:10x3 | 1e:10x3], x2: (Z,9) = [0e | 1o:3 | 2e:5]
// weights: (Z,4344), out: (Z,156) = [r0e:48 | r1o:30 | r1e:30 | r0o:48]

#define NS 48
#define NV 10
#define WNUM 4344
#define OUTDIM 156

// weight offsets (floats) within a sample's 4344-float blob
#define OFF_W00   0
#define OFF_W01   2304
#define OFF_W10   2784
#define OFF_W110  2884
#define OFF_W112  3364
#define OFF_W12   3464
#define OFF_W20   3564
#define OFF_W211  3664
#define OFF_W213  3764
#define OFF_W22   4244

// normalization constants
#define N0E  0.13130643285972254f   // sqrt(1/58)
#define N1O  0.19611613513818404f   // sqrt(3/78)
#define N1E  0.31622776601683794f   // sqrt(1/10)
#define N0O  0.31622776601683794f   // sqrt(1/10)
#define ISQ3 0.57735026918962576f   // 1/sqrt(3)
#define ISQ6 0.40824829046386302f   // 1/sqrt(6)
#define S10  0.31622776601683794f   // 1/sqrt(10)
#define S30  0.18257418583505537f   // 1/sqrt(30)

__global__ __launch_bounds__(192) void tp_third_kernel(
    const float* __restrict__ x1,
    const float* __restrict__ x2,
    const float* __restrict__ wts,
    float* __restrict__ out)
{
    const int z = blockIdx.x;
    const int t = threadIdx.x;

    __shared__ float sx1[108];
    __shared__ float sx2[9];
    __shared__ float s_a00[48];      // N0E * x2_0e * x1_0e[u]           -> r0e
    __shared__ float s_a110[10];     // N0E*ISQ3 * dot(x1_1o[u], x2_1o)  -> r0e
    __shared__ float s_a213[10];     // N0O*ISQ3 * dot(x1_1e[u], x2_1o)  -> r0o
    __shared__ float s_v10[30];      // N1O*ISQ3 * x2_0e * x1_1o[u]      -> r1o
    __shared__ float s_v12[30];      // N1O * w3j121(x1_1o[u], x2_2e)    -> r1o
    __shared__ float s_v211[30];     // N1O/sqrt6 * cross(x1_1e[u],x2_1o)-> r1o
    __shared__ float s_v112[30];     // N1E/sqrt6 * cross(x1_1o[u],x2_1o)-> r1e
    __shared__ float s_v20[30];      // N1E*ISQ3 * x2_0e * x1_1e[u]      -> r1e
    __shared__ float s_v22[30];      // N1E * w3j121(x1_1e[u], x2_2e)    -> r1e

    // ---- phase 1: stage small inputs ----
    if (t < 108)       sx1[t]       = x1[(size_t)z * 108 + t];
    else if (t < 117)  sx2[t - 108] = x2[(size_t)z * 9 + (t - 108)];
    __syncthreads();

    // ---- phase 2: precompute left-operand vectors ----
    const float e0 = sx2[0];
    const float b0 = sx2[1], b1 = sx2[2], b2 = sx2[3];
    const float c0 = sx2[4], c1 = sx2[5], c2 = sx2[6], c3 = sx2[7], c4 = sx2[8];

    if (t < 48) {
        s_a00[t] = N0E * e0 * sx1[t];
    } else if (t < 58) {
        const int u = t - 48;
        const float a0 = sx1[48 + u * 3 + 0];
        const float a1 = sx1[48 + u * 3 + 1];
        const float a2 = sx1[48 + u * 3 + 2];
        s_a110[u] = N0E * ISQ3 * (a0 * b0 + a1 * b1 + a2 * b2);
        s_v10[u * 3 + 0] = N1O * ISQ3 * e0 * a0;
        s_v10[u * 3 + 1] = N1O * ISQ3 * e0 * a1;
        s_v10[u * 3 + 2] = N1O * ISQ3 * e0 * a2;
        s_v112[u * 3 + 0] = N1E * ISQ6 * (a1 * b2 - a2 * b1);
        s_v112[u * 3 + 1] = N1E * ISQ6 * (a2 * b0 - a0 * b2);
        s_v112[u * 3 + 2] = N1E * ISQ6 * (a0 * b1 - a1 * b0);
        const float g0 = S10 * a2 * c0 - S30 * a0 * c2 - S10 * a0 * c4 + S10 * a1 * c1;
        const float g1 = S10 * a2 * c3 + S10 * a0 * c1 + 2.0f * S30 * a1 * c2;
        const float g2 = -S30 * a2 * c2 + S10 * a2 * c4 + S10 * a0 * c0 + S10 * a1 * c3;
        s_v12[u * 3 + 0] = N1O * g0;
        s_v12[u * 3 + 1] = N1O * g1;
        s_v12[u * 3 + 2] = N1O * g2;
    } else if (t < 68) {
        const int u = t - 58;
        const float a0 = sx1[78 + u * 3 + 0];
        const float a1 = sx1[78 + u * 3 + 1];
        const float a2 = sx1[78 + u * 3 + 2];
        s_a213[u] = N0O * ISQ3 * (a0 * b0 + a1 * b1 + a2 * b2);
        s_v20[u * 3 + 0] = N1E * ISQ3 * e0 * a0;
        s_v20[u * 3 + 1] = N1E * ISQ3 * e0 * a1;
        s_v20[u * 3 + 2] = N1E * ISQ3 * e0 * a2;
        s_v211[u * 3 + 0] = N1O * ISQ6 * (a1 * b2 - a2 * b1);
        s_v211[u * 3 + 1] = N1O * ISQ6 * (a2 * b0 - a0 * b2);
        s_v211[u * 3 + 2] = N1O * ISQ6 * (a0 * b1 - a1 * b0);
        const float g0 = S10 * a2 * c0 - S30 * a0 * c2 - S10 * a0 * c4 + S10 * a1 * c1;
        const float g1 = S10 * a2 * c3 + S10 * a0 * c1 + 2.0f * S30 * a1 * c2;
        const float g2 = -S30 * a2 * c2 + S10 * a2 * c4 + S10 * a0 * c0 + S10 * a1 * c3;
        s_v22[u * 3 + 0] = N1E * g0;
        s_v22[u * 3 + 1] = N1E * g1;
        s_v22[u * 3 + 2] = N1E * g2;
    }
    __syncthreads();

    // ---- phase 3: direct-gmem column matvecs, warp-aligned output groups ----
    const float* __restrict__ W = wts + (size_t)z * WNUM;
    float* __restrict__ o = out + (size_t)z * OUTDIM;

    if (t < 64) {
        // warps 0-1: r0e[w] : w00 (48x48) + w110 (10x48)
        if (t < 48) {
            const int w = t;
            float acc = 0.0f;
            #pragma unroll 12
            for (int u = 0; u < 48; u++) acc += s_a00[u] * W[OFF_W00 + u * 48 + w];
            #pragma unroll
            for (int u = 0; u < 10; u++) acc += s_a110[u] * W[OFF_W110 + u * 48 + w];
            o[w] = acc;
        }
    } else if (t < 128) {
        // warps 2-3: r0o[w] : w213 (10x48)
        const int w = t - 64;
        if (w < 48) {
            float acc = 0.0f;
            #pragma unroll
            for (int u = 0; u < 10; u++) acc += s_a213[u] * W[OFF_W213 + u * 48 + w];
            o[108 + w] = acc;
        }
    } else if (t < 160) {
        // warp 4: r1o[w,j] : w01 (48x10) split over j via shuffle + w10/w12/w211
        const int idx = t - 128;               // lane id, 0..31 (30 active)
        const int w = idx / 3, j = idx - w * 3;
        const int wc = (w > 9) ? 9 : w;        // clamp lanes 30,31 (results discarded)
        // each j-thread sums u = 3i + j -> per-iteration the warp reads 30
        // CONSECUTIVE floats of w01 (each element exactly once)
        float p = 0.0f;
        #pragma unroll
        for (int i = 0; i < 16; i++) {
            const int u = 3 * i + j;
            p += sx1[u] * W[OFF_W01 + u * 10 + wc];
        }
        const int base = w * 3;
        float ts = __shfl_sync(0xFFFFFFFFu, p, base)
                 + __shfl_sync(0xFFFFFFFFu, p, base + 1)
                 + __shfl_sync(0xFFFFFFFFu, p, base + 2);
        float acc = (N1O * ISQ3) * sx2[1 + j] * ts;
        #pragma unroll
        for (int u = 0; u < 10; u++) {
            acc += s_v10[u * 3 + j]  * W[OFF_W10  + u * 10 + wc];
            acc += s_v12[u * 3 + j]  * W[OFF_W12  + u * 10 + wc];
            acc += s_v211[u * 3 + j] * W[OFF_W211 + u * 10 + wc];
        }
        if (idx < 30) o[48 + w * 3 + j] = acc;
    } else {
        // warp 5: r1e[w,j] : w112 + w20 + w22 (10x10)
        const int idx = t - 160;
        if (idx < 30) {
            const int w = idx / 3, j = idx - w * 3;
            float acc = 0.0f;
            #pragma unroll
            for (int u = 0; u < 10; u++) {
                acc += s_v112[u * 3 + j] * W[OFF_W112 + u * 10 + w];
                acc += s_v20[u * 3 + j]  * W[OFF_W20  + u * 10 + w];
                acc += s_v22[u * 3 + j]  * W[OFF_W22  + u * 10 + w];
            }
            o[78 + w * 3 + j] = acc;
        }
    }
}

extern "C" void kernel_launch(void* const* d_in, const int* in_sizes, int n_in,
                              void* d_out, int out_size) {
    const float* x1  = (const float*)d_in[0];
    const float* x2  = (const float*)d_in[1];
    const float* wts = (const float*)d_in[2];
    float* out = (float*)d_out;
    const int Z = in_sizes[0] / 108;
    tp_third_kernel<<<Z, 192>>>(x1, x2, wts, out);
}

// round 4
// speedup vs baseline: 1.2762x; 1.1960x over previous
#include <cuda_runtime.h>
#include <cstdint>

// TPThird: e3nn-style tensor product, Z=50000 samples.
// x1: (Z,108) = [0e:48 | 1o:10x3 | 1e:10x3], x2: (Z,9) = [0e | 1o:3 | 2e:5]
// weights: (Z,4344), out: (Z,156) = [r0e:48 | r1o:30 | r1e:30 | r0o:48]

#define NS 48
#define NV 10
#define WNUM 4344
#define WBYTES (WNUM * 4)
#define OUTDIM 156

#define OFF_W00   0
#define OFF_W01   2304
#define OFF_W10   2784
#define OFF_W110  2884
#define OFF_W112  3364
#define OFF_W12   3464
#define OFF_W20   3564
#define OFF_W211  3664
#define OFF_W213  3764
#define OFF_W22   4244

#define N0E  0.13130643285972254f   // sqrt(1/58)
#define N1O  0.19611613513818404f   // sqrt(3/78)
#define N1E  0.31622776601683794f   // sqrt(1/10)
#define N0O  0.31622776601683794f   // sqrt(1/10)
#define ISQ3 0.57735026918962576f   // 1/sqrt(3)
#define ISQ6 0.40824829046386302f   // 1/sqrt(6)
#define S10  0.31622776601683794f   // 1/sqrt(10)
#define S30  0.18257418583505537f   // 1/sqrt(30)

__device__ __forceinline__ uint32_t smem_u32(const void* p) {
    uint32_t a;
    asm("{ .reg .u64 t; cvta.to.shared.u64 t, %1; cvt.u32.u64 %0, t; }"
        : "=r"(a) : "l"(p));
    return a;
}

__global__ __launch_bounds__(192) void tp_third_kernel(
    const float* __restrict__ x1,
    const float* __restrict__ x2,
    const float* __restrict__ wts,
    float* __restrict__ out)
{
    const int z = blockIdx.x;
    const int t = threadIdx.x;

    __shared__ alignas(128) float sw[WNUM];   // 17376 B weight stage (TMA bulk)
    __shared__ alignas(8) unsigned long long mbar;
    __shared__ float sx1[108];
    __shared__ float sx2[9];
    __shared__ float s_a00[48];
    __shared__ float s_a110[10];
    __shared__ float s_a213[10];
    __shared__ float s_v10[30];
    __shared__ float s_v12[30];
    __shared__ float s_v211[30];
    __shared__ float s_v112[30];
    __shared__ float s_v20[30];
    __shared__ float s_v22[30];

    const uint32_t mbar_a = smem_u32(&mbar);
    const uint32_t sw_a   = smem_u32(sw);

    // ---- init mbarrier ----
    if (t == 0) {
        asm volatile("mbarrier.init.shared.b64 [%0], 1;" :: "r"(mbar_a) : "memory");
    }
    // stage small inputs concurrently
    if (t < 108)       sx1[t]       = x1[(size_t)z * 108 + t];
    else if (t < 117)  sx2[t - 108] = x2[(size_t)z * 9 + (t - 108)];
    __syncthreads();

    // ---- kick off bulk weight copy (whole blob in flight at once) ----
    if (t == 0) {
        const void* src = (const void*)(wts + (size_t)z * WNUM);
        asm volatile("mbarrier.arrive.expect_tx.shared.b64 _, [%0], %1;"
                     :: "r"(mbar_a), "r"((uint32_t)WBYTES) : "memory");
        asm volatile(
            "cp.async.bulk.shared::cluster.global.mbarrier::complete_tx::bytes "
            "[%0], [%1], %2, [%3];"
            :: "r"(sw_a), "l"(src), "r"((uint32_t)WBYTES), "r"(mbar_a)
            : "memory");
    }

    // ---- phase 2 (overlapped with the bulk copy): left-operand vectors ----
    const float e0 = sx2[0];
    const float b0 = sx2[1], b1 = sx2[2], b2 = sx2[3];
    const float c0 = sx2[4], c1 = sx2[5], c2 = sx2[6], c3 = sx2[7], c4 = sx2[8];

    if (t < 48) {
        s_a00[t] = N0E * e0 * sx1[t];
    } else if (t < 58) {
        const int u = t - 48;
        const float a0 = sx1[48 + u * 3 + 0];
        const float a1 = sx1[48 + u * 3 + 1];
        const float a2 = sx1[48 + u * 3 + 2];
        s_a110[u] = N0E * ISQ3 * (a0 * b0 + a1 * b1 + a2 * b2);
        s_v10[u * 3 + 0] = N1O * ISQ3 * e0 * a0;
        s_v10[u * 3 + 1] = N1O * ISQ3 * e0 * a1;
        s_v10[u * 3 + 2] = N1O * ISQ3 * e0 * a2;
        s_v112[u * 3 + 0] = N1E * ISQ6 * (a1 * b2 - a2 * b1);
        s_v112[u * 3 + 1] = N1E * ISQ6 * (a2 * b0 - a0 * b2);
        s_v112[u * 3 + 2] = N1E * ISQ6 * (a0 * b1 - a1 * b0);
        const float g0 = S10 * a2 * c0 - S30 * a0 * c2 - S10 * a0 * c4 + S10 * a1 * c1;
        const float g1 = S10 * a2 * c3 + S10 * a0 * c1 + 2.0f * S30 * a1 * c2;
        const float g2 = -S30 * a2 * c2 + S10 * a2 * c4 + S10 * a0 * c0 + S10 * a1 * c3;
        s_v12[u * 3 + 0] = N1O * g0;
        s_v12[u * 3 + 1] = N1O * g1;
        s_v12[u * 3 + 2] = N1O * g2;
    } else if (t < 68) {
        const int u = t - 58;
        const float a0 = sx1[78 + u * 3 + 0];
        const float a1 = sx1[78 + u * 3 + 1];
        const float a2 = sx1[78 + u * 3 + 2];
        s_a213[u] = N0O * ISQ3 * (a0 * b0 + a1 * b1 + a2 * b2);
        s_v20[u * 3 + 0] = N1E * ISQ3 * e0 * a0;
        s_v20[u * 3 + 1] = N1E * ISQ3 * e0 * a1;
        s_v20[u * 3 + 2] = N1E * ISQ3 * e0 * a2;
        s_v211[u * 3 + 0] = N1O * ISQ6 * (a1 * b2 - a2 * b1);
        s_v211[u * 3 + 1] = N1O * ISQ6 * (a2 * b0 - a0 * b2);
        s_v211[u * 3 + 2] = N1O * ISQ6 * (a0 * b1 - a1 * b0);
        const float g0 = S10 * a2 * c0 - S30 * a0 * c2 - S10 * a0 * c4 + S10 * a1 * c1;
        const float g1 = S10 * a2 * c3 + S10 * a0 * c1 + 2.0f * S30 * a1 * c2;
        const float g2 = -S30 * a2 * c2 + S10 * a2 * c4 + S10 * a0 * c0 + S10 * a1 * c3;
        s_v22[u * 3 + 0] = N1E * g0;
        s_v22[u * 3 + 1] = N1E * g1;
        s_v22[u * 3 + 2] = N1E * g2;
    }
    __syncthreads();

    // ---- wait for weight blob (acquire orders smem reads after TMA writes) ----
    {
        asm volatile(
            "{\n\t"
            ".reg .pred P;\n\t"
            "WAIT_%=:\n\t"
            "mbarrier.try_wait.parity.acquire.cta.shared::cta.b64 P, [%0], 0, 0x989680;\n\t"
            "@!P bra WAIT_%=;\n\t"
            "}"
            :: "r"(mbar_a) : "memory");
    }

    // ---- phase 3: column matvecs from smem, warp-aligned output groups ----
    float* __restrict__ o = out + (size_t)z * OUTDIM;

    if (t < 64) {
        // warps 0-1: r0e[w] : w00 (48x48) + w110 (10x48)
        if (t < 48) {
            const int w = t;
            float acc = 0.0f;
            #pragma unroll
            for (int u = 0; u < 48; u++) acc += s_a00[u] * sw[OFF_W00 + u * 48 + w];
            #pragma unroll
            for (int u = 0; u < 10; u++) acc += s_a110[u] * sw[OFF_W110 + u * 48 + w];
            o[w] = acc;
        }
    } else if (t < 128) {
        // warps 2-3: r0o[w] : w213 (10x48)
        const int w = t - 64;
        if (w < 48) {
            float acc = 0.0f;
            #pragma unroll
            for (int u = 0; u < 10; u++) acc += s_a213[u] * sw[OFF_W213 + u * 48 + w];
            o[108 + w] = acc;
        }
    } else if (t < 160) {
        // warp 4: r1o[w,j] : w01 (48x10) split over j via shuffle + w10/w12/w211
        const int idx = t - 128;
        const int w = idx / 3, j = idx - w * 3;
        const int wc = (w > 9) ? 9 : w;
        float p = 0.0f;
        #pragma unroll
        for (int i = 0; i < 16; i++) {
            const int u = 3 * i + j;
            p += sx1[u] * sw[OFF_W01 + u * 10 + wc];
        }
        const int base = w * 3;
        float ts = __shfl_sync(0xFFFFFFFFu, p, base)
                 + __shfl_sync(0xFFFFFFFFu, p, base + 1)
                 + __shfl_sync(0xFFFFFFFFu, p, base + 2);
        float acc = (N1O * ISQ3) * sx2[1 + j] * ts;
        #pragma unroll
        for (int u = 0; u < 10; u++) {
            acc += s_v10[u * 3 + j]  * sw[OFF_W10  + u * 10 + wc];
            acc += s_v12[u * 3 + j]  * sw[OFF_W12  + u * 10 + wc];
            acc += s_v211[u * 3 + j] * sw[OFF_W211 + u * 10 + wc];
        }
        if (idx < 30) o[48 + w * 3 + j] = acc;
    } else {
        // warp 5: r1e[w,j] : w112 + w20 + w22 (10x10)
        const int idx = t - 160;
        if (idx < 30) {
            const int w = idx / 3, j = idx - w * 3;
            float acc = 0.0f;
            #pragma unroll
            for (int u = 0; u < 10; u++) {
                acc += s_v112[u * 3 + j] * sw[OFF_W112 + u * 10 + w];
                acc += s_v20[u * 3 + j]  * sw[OFF_W20  + u * 10 + w];
                acc += s_v22[u * 3 + j]  * sw[OFF_W22  + u * 10 + w];
            }
            o[78 + w * 3 + j] = acc;
        }
    }
}

extern "C" void kernel_launch(void* const* d_in, const int* in_sizes, int n_in,
                              void* d_out, int out_size) {
    const float* x1  = (const float*)d_in[0];
    const float* x2  = (const float*)d_in[1];
    const float* wts = (const float*)d_in[2];
    float* out = (float*)d_out;
    const int Z = in_sizes[0] / 108;
    tp_third_kernel<<<Z, 192>>>(x1, x2, wts, out);
}